// round 16
// baseline (speedup 1.0000x reference)
#include <cuda_runtime.h>
#include <math.h>

#define B 64
#define T 4096
#define D 512
#define NSPLIT 32                // CTAs per batch in partial kernel
#define NPART NSPLIT             // one partial per CTA
#define CTA_ROWS 128             // T/NSPLIT rows per CTA
#define BATCH 8
#define NBATCH (CTA_ROWS / BATCH)

#define KD 32                    // key kernel: d-columns per CTA
#define KB 32                    // key kernel: batches per CTA
#define KZ 16                    // key kernel: split-K factor
#define KSLICE (D / KZ)          // 32 floats per K slice
#define QP4 9                    // smem pitch in float4 (odd -> conflict-free)

// Scratch (static device globals: allocation-free)
__device__ float g_kpart[KZ * B * D];                // 2 MB (split-K partials)
__device__ float g_key[B * D];                       // 128 KB (folded key)
__device__ float g_pm[B * NPART];
__device__ float g_ps[B * NPART];
__device__ float g_pc[(size_t)B * NPART * D];        // 4.2 MB
__device__ int   g_mask_kind;                        // 0=int32, 1=uint8, 2=float32

// ---------------------------------------------------------------------------
// Kernel 1: split-K key GEMM (unchanged).
// ---------------------------------------------------------------------------
__global__ __launch_bounds__(256) void key_kernel(const float* __restrict__ q,
                                                  const float* __restrict__ W,
                                                  const float* __restrict__ bias,
                                                  const unsigned int* __restrict__ mw) {
    if (blockIdx.x == 0 && blockIdx.y == 0 && blockIdx.z == 0) {
        int kind = 0;
        for (int i = threadIdx.x; i < 2048; i += blockDim.x) {
            unsigned int w = mw[i];
            if (w == 0x3f800000u)            kind = 2;                    // float 1.0f
            else if ((w & 0xFFFFFF00u) != 0) kind = kind > 1 ? kind : 1;  // high byte set
        }
        if (kind) atomicMax(&g_mask_kind, kind);   // stays 0 => int32
    }

    __shared__ float4 qs[KB * QP4];

    const int b0 = blockIdx.y * KB;
    const int d0 = blockIdx.x * KD;
    const int k0 = blockIdx.z * KSLICE;

    {
        int row = threadIdx.x >> 3;
        int col = threadIdx.x & 7;
        qs[row * QP4 + col] =
            *reinterpret_cast<const float4*>(q + (size_t)(b0 + row) * D + k0 + 4 * col);
    }
    __syncthreads();

    const int warp = threadIdx.x >> 5;
    const int lane = threadIdx.x & 31;
    const int d    = d0 + warp * 4 + (lane >> 3);
    const int bl   = lane & 7;

    const float4* wrow = reinterpret_cast<const float4*>(W + (size_t)d * D + k0);

    float4 acc[4];
#pragma unroll
    for (int u = 0; u < 4; u++) acc[u] = make_float4(0.f, 0.f, 0.f, 0.f);

#pragma unroll
    for (int j = 0; j < KSLICE / 4; j++) {
        float4 wv = wrow[j];
#pragma unroll
        for (int u = 0; u < 4; u++) {
            float4 qv = qs[(bl + 8 * u) * QP4 + j];
            acc[u].x = fmaf(wv.x, qv.x, acc[u].x);
            acc[u].y = fmaf(wv.y, qv.y, acc[u].y);
            acc[u].z = fmaf(wv.z, qv.z, acc[u].z);
            acc[u].w = fmaf(wv.w, qv.w, acc[u].w);
        }
    }

    const float bd = (blockIdx.z == 0) ? bias[d] : 0.f;
#pragma unroll
    for (int u = 0; u < 4; u++) {
        float r = (acc[u].x + acc[u].y) + (acc[u].z + acc[u].w) + bd;
        g_kpart[blockIdx.z * (B * D) + (size_t)(b0 + bl + 8 * u) * D + d] = r;
    }
}

// ---------------------------------------------------------------------------
// Kernel 1b: fold split-K slices into g_key once (unchanged).
// ---------------------------------------------------------------------------
__global__ __launch_bounds__(256) void fold_kernel() {
    const int i = blockIdx.x * 256 + threadIdx.x;
    float s = 0.f;
#pragma unroll
    for (int z = 0; z < KZ; z++)
        s += g_kpart[z * (B * D) + i];
    g_key[i] = s;
}

// ---------------------------------------------------------------------------
// Kernel 2 REDESIGN: CTA-wide row processing for minimal per-thread state.
// 128 threads per CTA; thread owns D-columns [4*tid, 4*tid+4) (one float4).
// Per 8-row batch:
//   1. 8 predicated, independent, 512B-coalesced LDG.128 per thread (MLP=8)
//   2. 8 partial dots -> smem [8][128]
//   3. the 4 warps reduce 2 rows EACH in parallel (shuffle chains overlap)
//   4. CTA-uniform batch-8 online softmax update (exact algebra)
// Per-thread regs ~75 (vs ~150) -> ~24 warps/SM: latency hidden by TLP.
// All-masked batches (byte==0, CTA-uniform) skip loads and barriers.
// No end-of-kernel merge: each thread owns unique columns, writes g_pc direct.
// ---------------------------------------------------------------------------
__global__ __launch_bounds__(128) void partial_kernel(const float* __restrict__ A,
                                                      const void* __restrict__ mask_raw) {
    const int b     = blockIdx.x / NSPLIT;
    const int split = blockIdx.x % NSPLIT;
    const int tid   = threadIdx.x;
    const int warp  = tid >> 5;
    const int lane  = tid & 31;
    const int t0    = split * CTA_ROWS;

    __shared__ unsigned s_act[4];        // row-active bitmap, 128 bits
    __shared__ float    psc[BATCH * 128];
    __shared__ float    s_score[BATCH];

    // mask for row t0+tid (one row per thread)
    {
        const size_t midx = (size_t)(t0 + tid) * B + b;
        const int kind = g_mask_kind;
        bool masked;
        if (kind == 1)      masked = ((const unsigned char*)mask_raw)[midx] != 0;
        else if (kind == 0) masked = ((const int*)mask_raw)[midx] != 0;
        else                masked = ((const float*)mask_raw)[midx] != 0.f;
        unsigned bal = __ballot_sync(0xffffffffu, !masked);
        if (lane == 0) s_act[warp] = bal;
    }
    __syncthreads();

    const float4 kf = *reinterpret_cast<const float4*>(g_key + b * D + 4 * tid);

    float m = -INFINITY, s = 0.f;
    float4 c = make_float4(0.f, 0.f, 0.f, 0.f);
    float4 buf[BATCH];
#pragma unroll
    for (int r = 0; r < BATCH; r++) buf[r] = make_float4(0.f, 0.f, 0.f, 0.f);

    const float* base = A + ((size_t)b * T + t0) * D + 4 * tid;

    for (int bt = 0; bt < NBATCH; bt++) {
        // CTA-uniform activity byte for this batch (from smem bitmap)
        const unsigned byte = (s_act[bt >> 2] >> ((bt & 3) * 8)) & 0xFFu;
        if (byte == 0u) continue;                    // uniform skip, bars skipped too

        const int r0 = bt * BATCH;

        // 1. predicated loads: 8 independent coalesced LDG.128
#pragma unroll
        for (int r = 0; r < BATCH; r++) {
            if ((byte >> r) & 1u)
                buf[r] = __ldcs(reinterpret_cast<const float4*>(base + (size_t)(r0 + r) * D));
        }

        // 2. partial dots -> smem
#pragma unroll
        for (int r = 0; r < BATCH; r++) {
            float p = buf[r].x * kf.x + buf[r].y * kf.y
                    + buf[r].z * kf.z + buf[r].w * kf.w;
            psc[r * 128 + tid] = p;
        }
        __syncthreads();

        // 3. each warp reduces 2 rows (parallel across warps)
#pragma unroll
        for (int rr = 0; rr < 2; rr++) {
            const int r = 2 * warp + rr;
            float4 v4 = *reinterpret_cast<float4*>(&psc[r * 128 + 4 * lane]);
            float v = (v4.x + v4.y) + (v4.z + v4.w);
#pragma unroll
            for (int off = 16; off > 0; off >>= 1)
                v += __shfl_xor_sync(0xffffffffu, v, off);
            if (lane == 0) s_score[r] = v;
        }
        __syncthreads();

        // 4. batch-8 online softmax update (all threads redundantly, identical)
        float mn = m;
        float sv[BATCH];
#pragma unroll
        for (int r = 0; r < BATCH; r++) {
            sv[r] = s_score[r];
            if ((byte >> r) & 1u) mn = fmaxf(mn, sv[r]);
        }
        const float alpha = (m == -INFINITY) ? 0.f : __expf(m - mn);
        float w[BATCH], ws = 0.f;
#pragma unroll
        for (int r = 0; r < BATCH; r++) {
            w[r] = ((byte >> r) & 1u) ? __expf(sv[r] - mn) : 0.f;
            ws += w[r];
        }
        s = s * alpha + ws;
        float cx = c.x * alpha, cy = c.y * alpha, cz = c.z * alpha, cw = c.w * alpha;
#pragma unroll
        for (int r = 0; r < BATCH; r++) {
            cx = fmaf(w[r], buf[r].x, cx);
            cy = fmaf(w[r], buf[r].y, cy);
            cz = fmaf(w[r], buf[r].z, cz);
            cw = fmaf(w[r], buf[r].w, cw);
        }
        c = make_float4(cx, cy, cz, cw);
        m = mn;
    }

    const int pid = blockIdx.x;   // b*NSPLIT + split
    if (tid == 0) { g_pm[pid] = m; g_ps[pid] = s; }
    *reinterpret_cast<float4*>(g_pc + (size_t)pid * D + 4 * tid) = c;
}

// ---------------------------------------------------------------------------
// Kernel 3: combine 32 partials per batch (unchanged from R15: 512 CTAs x 128
// threads, 2 threads per column, shuffle-reduced scales).
// ---------------------------------------------------------------------------
__global__ __launch_bounds__(128) void reduce_kernel(float* __restrict__ out) {
    const int b    = blockIdx.x >> 3;
    const int part = blockIdx.x & 7;
    const int tid  = threadIdx.x;
    const int col  = tid & 63;
    const int half = tid >> 6;

    __shared__ float sc[NPART];
    __shared__ float Ssh;
    __shared__ float ps[128];

    if (tid < 32) {
        const float mi = g_pm[b * NPART + tid];
        float mm = mi;
#pragma unroll
        for (int off = 16; off > 0; off >>= 1)
            mm = fmaxf(mm, __shfl_xor_sync(0xffffffffu, mm, off));
        const float scale = (mi == -INFINITY) ? 0.f : __expf(mi - mm);
        sc[tid] = scale;
        float sv = scale * g_ps[b * NPART + tid];
#pragma unroll
        for (int off = 16; off > 0; off >>= 1)
            sv += __shfl_xor_sync(0xffffffffu, sv, off);
        if (tid == 0) Ssh = sv;
    }
    __syncthreads();

    const int d  = part * 64 + col;
    const int i0 = half * 16;
    float acc = 0.f;
    const float* pc = g_pc + (size_t)b * NPART * D + d;
#pragma unroll
    for (int i = 0; i < 16; i++)
        acc = fmaf(pc[(size_t)(i0 + i) * D], sc[i0 + i], acc);
    ps[tid] = acc;
    __syncthreads();
    if (half == 0)
        out[b * D + d] = (ps[tid] + ps[tid + 64]) / Ssh;
}

// ---------------------------------------------------------------------------
extern "C" void kernel_launch(void* const* d_in, const int* in_sizes, int n_in,
                              void* d_out, int out_size) {
    const float* q    = (const float*)d_in[0];   // [B, D]
    const float* A    = (const float*)d_in[1];   // [B, T, D]
    const void*  mask = d_in[2];                 // [T, B] bool-ish (dtype sniffed)
    const float* W    = (const float*)d_in[3];   // [D, D]
    const float* bias = (const float*)d_in[4];   // [D]
    float*       out  = (float*)d_out;           // [B, 1, D]

    key_kernel<<<dim3(D / KD, B / KB, KZ), 256>>>(q, W, bias, (const unsigned int*)mask);
    fold_kernel<<<(B * D) / 256, 256>>>();
    partial_kernel<<<B * NSPLIT, 128>>>(A, mask);
    reduce_kernel<<<B * 8, 128>>>(out);
}